// round 17
// baseline (speedup 1.0000x reference)
#include <cuda_runtime.h>
#include <cuda_bf16.h>

// Reference: |jnp.sum(x) - jnp.sum(x)| > 1e-6  ==  False, always.
// Output is the constant scalar 0; the 256 MiB input is never read.
//
// Measurement matrix for the single mandatory output-write node:
//   kernel node  : 4.608us          (R2)
//   memset node  : {3.232..3.968}us (R5,R6,R8,R9,R12,R15 — bimodal jitter)
//   memcpy node  : THIS ROUND — the one unmeasured node type.
// Source is a __device__ global zero word (module storage, not a runtime
// allocation). 4 zero bytes written to d_out, byte-identical result to all
// passing rounds. Prediction: neutral-to-slower than memset; measuring to
// close the matrix rather than re-roll harness noise on identical source.

__device__ unsigned int g_zero_src[64] = {0};  // zero-initialized module storage

extern "C" void kernel_launch(void* const* d_in, const int* in_sizes, int n_in,
                              void* d_out, int out_size) {
    (void)d_in; (void)in_sizes; (void)n_in;
    size_t bytes = (out_size > 0 ? (size_t)out_size : 1) * 4u;
    if (bytes > sizeof(g_zero_src)) bytes = sizeof(g_zero_src);
    void* src = nullptr;
    cudaGetSymbolAddress(&src, g_zero_src);
    cudaMemcpyAsync(d_out, src, bytes, cudaMemcpyDeviceToDevice, 0);
}